// round 13
// baseline (speedup 1.0000x reference)
#include <cuda_runtime.h>
#include <cstdint>

#define N 2048
#define D 1024
#define GCE_Q 0.7f
#define EPS 1e-8f
#define INV_LN2 1.4426950408889634f
#define LN2 0.6931471805599453f
#define EPS2 (EPS * INV_LN2)

#define CP2 20   // interleaved exp row stride: 10 classes x 2 heads
#define CPS 13   // scalar raw row stride (odd -> conflict-free)

typedef unsigned long long ull;

// -------- device scratch (no allocations) --------
// All log-domain tables stored in log2 units (divided by ln2).
__device__ __align__(16) float g_iEA2[N * CP2];  // i-side interleaved exp(v-m): [row][c][head]
__device__ __align__(16) float g_jEB2[N * CP2];  // j-side interleaved
__device__ float g_iAbpM[N * CPS];               // (Ab'[i,c] - mAb[i]) / ln2
__device__ __align__(16) float2 g_jCB[N * 10];   // ((mBc - Bc[j,c])/ln2, (mBb - Bb[j,c])/ln2)
__device__ float g_iacyM[N];                     // (Ac'[i,y[i]] - mAc[i]) / ln2
__device__ float g_iabyM[N];                     // (Ab'[i,y[i]] - mAb[i]) / ln2
__device__ float g_jbbyM[N];                     // (Bb[j,y[j]] - mBb[j]) / ln2

__device__ __forceinline__ void fma2(ull& acc, ull a, ull b) {
    asm("fma.rn.f32x2 %0, %1, %2, %0;" : "+l"(acc) : "l"(a), "l"(b));
}
__device__ __forceinline__ float f2lo(ull v) {
    return __uint_as_float((unsigned)(v & 0xffffffffull));
}
__device__ __forceinline__ float f2hi(ull v) {
    return __uint_as_float((unsigned)(v >> 32));
}
__device__ __forceinline__ float ex2f(float x) {
    float r;
    asm("ex2.approx.ftz.f32 %0, %1;" : "=f"(r) : "f"(x));
    return r;
}
__device__ __forceinline__ float lg2f(float x) {
    float r;
    asm("lg2.approx.ftz.f32 %0, %1;" : "=f"(r) : "f"(x));
    return r;
}

// ============================================================
// Kernel 1 (R10 exact, measured ~7.9us): 8 rows/block, 128 thr,
// thread-owns-column GEMM, stride-85 smem reduce, log2 tail.
// ============================================================
#define K1_ROWS 8
#define K1_THR 128
#define RSTR 85

__global__ void __launch_bounds__(K1_THR) rowstats_kernel(
    const float* __restrict__ zc, const float* __restrict__ zb,
    const float* __restrict__ Wc, const float* __restrict__ bc,
    const float* __restrict__ Wb, const float* __restrict__ bb,
    const int* __restrict__ y)
{
    __shared__ float red[K1_THR * RSTR];     // 43.5 KB partials
    __shared__ float vals[K1_ROWS][20];      // reduced raw logits

    const int t = threadIdx.x;
    const int vr0 = blockIdx.x * K1_ROWS;
    const int side = vr0 >> 11;
    const int grow0 = vr0 & (N - 1);

    const float4* z4 = (const float4*)((side ? zb : zc) + (size_t)grow0 * D);

    for (int h = 0; h < 2; h++) {
        const float4* w4 = (const float4*)(h ? Wb : Wc);
        float acc[K1_ROWS][10];
#pragma unroll
        for (int r = 0; r < K1_ROWS; r++)
#pragma unroll
            for (int c = 0; c < 10; c++) acc[r][c] = 0.f;

#pragma unroll
        for (int kk = 0; kk < 2; kk++) {
            const int d4 = t + kk * K1_THR;
            float4 zv[K1_ROWS];
#pragma unroll
            for (int r = 0; r < K1_ROWS; r++) zv[r] = z4[r * 256 + d4];
#pragma unroll
            for (int c = 0; c < 10; c++) {
                const float4 wv = w4[c * 256 + d4];
#pragma unroll
                for (int r = 0; r < K1_ROWS; r++) {
                    acc[r][c] = fmaf(zv[r].x, wv.x,
                                fmaf(zv[r].y, wv.y,
                                fmaf(zv[r].z, wv.z,
                                fmaf(zv[r].w, wv.w, acc[r][c]))));
                }
            }
        }

#pragma unroll
        for (int r = 0; r < K1_ROWS; r++)
#pragma unroll
            for (int c = 0; c < 10; c++)
                red[t * RSTR + r * 10 + c] = acc[r][c];
        __syncthreads();

        if (t < 80) {
            float s0 = 0.f, s1 = 0.f, s2 = 0.f, s3 = 0.f;
#pragma unroll 8
            for (int u = 0; u < K1_THR; u += 4) {
                s0 += red[(u + 0) * RSTR + t];
                s1 += red[(u + 1) * RSTR + t];
                s2 += red[(u + 2) * RSTR + t];
                s3 += red[(u + 3) * RSTR + t];
            }
            vals[t / 10][h * 10 + t % 10] = (s0 + s1) + (s2 + s3);
        }
        __syncthreads();
    }

    if (t < K1_ROWS) {
        const int row = grow0 + t;
        float v[20];
#pragma unroll
        for (int k = 0; k < 20; k++) v[k] = vals[t][k];
        if (side == 0) {
#pragma unroll
            for (int k = 0; k < 10; k++) { v[k] += bc[k]; v[10 + k] += bb[k]; }
        }
#pragma unroll
        for (int k = 0; k < 20; k++) v[k] *= INV_LN2;
        float mc = v[0], mb = v[10];
#pragma unroll
        for (int k = 1; k < 10; k++) {
            mc = fmaxf(mc, v[k]);
            mb = fmaxf(mb, v[10 + k]);
        }
        const int yr = y[row];
        if (side == 0) {
#pragma unroll
            for (int c = 0; c < 10; c++) {
                g_iEA2[row * CP2 + 2 * c]     = ex2f(v[c] - mc);
                g_iEA2[row * CP2 + 2 * c + 1] = ex2f(v[10 + c] - mb);
                g_iAbpM[row * CPS + c] = v[10 + c] - mb;
            }
            g_iacyM[row] = v[yr] - mc;
            g_iabyM[row] = v[10 + yr] - mb;
        } else {
#pragma unroll
            for (int c = 0; c < 10; c++) {
                g_jEB2[row * CP2 + 2 * c]     = ex2f(v[c] - mc);
                g_jEB2[row * CP2 + 2 * c + 1] = ex2f(v[10 + c] - mb);
                g_jCB[row * 10 + c] = make_float2(mc - v[c], mb - v[10 + c]);
            }
            g_jbbyM[row] = v[10 + yr] - mb;
        }
    }
}

// ============================================================
// Kernel 2 v3: 64x128 per block (two 64x64 j-tiles), 256 thr,
// 4x4 per thread per tile. All staging up-front, one sync,
// two compute+epilogue passes. i-tables amortized over 2 tiles.
// ============================================================
__global__ void __launch_bounds__(256, 4) pair_kernel(
    const int* __restrict__ y, float* __restrict__ out)
{
    __shared__ __align__(16) float sEA2[64 * CP2];
    __shared__ __align__(16) float sEB2[2][64 * CP2];
    __shared__ __align__(16) ull   sCB[2][64 * 10];
    __shared__ float sAbpM[64 * CPS];
    __shared__ float sacyM[64], sabyM[64], sbbyM[2][64];
    __shared__ int   syi[64], syj[2][64];

    const int i0 = blockIdx.y * 64;
    const int j0 = blockIdx.x * 128;
    const int tid = threadIdx.x;

    for (int idx = tid; idx < 64 * (CP2 / 4); idx += 256)
        ((float4*)sEA2)[idx] = ((const float4*)g_iEA2)[i0 * (CP2 / 4) + idx];
    for (int idx = tid; idx < 2 * 64 * (CP2 / 4); idx += 256)
        ((float4*)sEB2[0])[idx] = ((const float4*)g_jEB2)[j0 * (CP2 / 4) + idx];
    for (int idx = tid; idx < 2 * 64 * 5; idx += 256)
        ((float4*)sCB[0])[idx] = ((const float4*)g_jCB)[j0 * 5 + idx];
    for (int idx = tid; idx < 64 * CPS; idx += 256)
        sAbpM[idx] = g_iAbpM[i0 * CPS + idx];
    if (tid < 64) {
        sacyM[tid] = g_iacyM[i0 + tid];
        sabyM[tid] = g_iabyM[i0 + tid];
        syi[tid]   = y[i0 + tid];
    } else if (tid < 192) {
        const int u = tid - 64;        // 0..127 -> two j-tiles
        sbbyM[u >> 6][u & 63] = g_jbbyM[j0 + u];
        syj[u >> 6][u & 63]   = y[j0 + u];
    }
    __syncthreads();

    const int tx = tid & 15;
    const int ty = tid >> 4;
    const int il = ty * 4;

    // hoist per-i scalars once for both tiles
    float acy[4], aby[4];
    int   yia[4];
#pragma unroll
    for (int a = 0; a < 4; a++) {
        acy[a] = sacyM[il + a];
        aby[a] = sabyM[il + a];
        yia[a] = syi[il + a];
    }
    ulonglong2 ea[5][4];
#pragma unroll
    for (int g = 0; g < 5; g++)
#pragma unroll
        for (int a = 0; a < 4; a++)
            ea[g][a] = *(const ulonglong2*)&sEA2[(il + a) * CP2 + g * 4];

    for (int tile = 0; tile < 2; tile++) {
        const float* EB = sEB2[tile];
        const ull*   CB = sCB[tile];

        ull acc[4][4];
#pragma unroll
        for (int a = 0; a < 4; a++)
#pragma unroll
            for (int b = 0; b < 4; b++) acc[a][b] = 0ull;

#pragma unroll
        for (int g = 0; g < 5; g++) {
            ulonglong2 eb[4];
#pragma unroll
            for (int b = 0; b < 4; b++)
                eb[b] = *(const ulonglong2*)&EB[(tx + 16 * b) * CP2 + g * 4];
#pragma unroll
            for (int a = 0; a < 4; a++)
#pragma unroll
                for (int b = 0; b < 4; b++) {
                    fma2(acc[a][b], ea[g][a].x, eb[b].x);
                    fma2(acc[a][b], ea[g][a].y, eb[b].y);
                }
        }

        float bby[4];
        int   yjb[4], jr[4];
#pragma unroll
        for (int b = 0; b < 4; b++) {
            jr[b]  = tx + 16 * b;
            bby[b] = sbbyM[tile][jr[b]];
            yjb[b] = syj[tile][jr[b]];
        }

#pragma unroll
        for (int a = 0; a < 4; a++) {
            float* orow = out + (size_t)(i0 + il + a) * N + j0 + tile * 64;
#pragma unroll
            for (int b = 0; b < 4; b++) {
                const float lc2 = lg2f(f2lo(acc[a][b]));
                const float lb2 = lg2f(f2hi(acc[a][b]));
                const ull  cb = CB[jr[b] * 10 + yia[a]];
                const float ce_pc2 = lc2 - acy[a] + f2lo(cb);
                const float ce_pb2 = lb2 - aby[a] + f2hi(cb);
                const float logp2  = sAbpM[(il + a) * CPS + yjb[b]] + bby[b] - lb2;
                const float gce2   = -logp2 * ex2f(GCE_Q * logp2);
                const float wr = __fdividef(ce_pb2, ce_pc2 + ce_pb2 + EPS2);
                orow[jr[b]] = fmaf(wr, ce_pc2 - gce2, gce2) * LN2;
            }
        }
    }
}

// ============================================================
extern "C" void kernel_launch(void* const* d_in, const int* in_sizes, int n_in,
                              void* d_out, int out_size)
{
    const float* zc = (const float*)d_in[0];  // [N, D]
    const float* zb = (const float*)d_in[1];  // [N, D]
    const float* Wc = (const float*)d_in[2];  // [C, D]
    const float* bc = (const float*)d_in[3];  // [C]
    const float* Wb = (const float*)d_in[4];  // [C, D]
    const float* bb = (const float*)d_in[5];  // [C]
    const int*   y  = (const int*)d_in[6];    // [N]
    float* out = (float*)d_out;               // [N, N]

    rowstats_kernel<<<(2 * N) / K1_ROWS, K1_THR>>>(zc, zb, Wc, bc, Wb, bb, y);

    dim3 g2(N / 128, N / 64);
    pair_kernel<<<g2, 256>>>(y, out);
}

// round 14
// speedup vs baseline: 2.4451x; 2.4451x over previous
#include <cuda_runtime.h>
#include <cstdint>

#define N 2048
#define D 1024
#define GCE_Q 0.7f
#define EPS 1e-8f
#define INV_LN2 1.4426950408889634f
#define LN2 0.6931471805599453f
#define EPS2 (EPS * INV_LN2)

#define CP2 20   // interleaved exp row stride: 10 classes x 2 heads
#define CPS 13   // scalar raw row stride (odd -> conflict-free)

typedef unsigned long long ull;

// -------- device scratch (no allocations) --------
// All log-domain tables stored in log2 units (divided by ln2).
__device__ __align__(16) float g_iEA2[N * CP2];  // i-side interleaved exp(v-m): [row][c][head]
__device__ __align__(16) float g_jEB2[N * CP2];  // j-side interleaved
__device__ float g_iAbpM[N * CPS];               // (Ab'[i,c] - mAb[i]) / ln2
__device__ __align__(16) float2 g_jCB[N * 10];   // ((mBc - Bc[j,c])/ln2, (mBb - Bb[j,c])/ln2)
__device__ float g_iacyM[N];                     // (Ac'[i,y[i]] - mAc[i]) / ln2
__device__ float g_iabyM[N];                     // (Ab'[i,y[i]] - mAb[i]) / ln2
__device__ float g_jbbyM[N];                     // (Bb[j,y[j]] - mBb[j]) / ln2

__device__ __forceinline__ void fma2(ull& acc, ull a, ull b) {
    asm("fma.rn.f32x2 %0, %1, %2, %0;" : "+l"(acc) : "l"(a), "l"(b));
}
__device__ __forceinline__ float f2lo(ull v) {
    return __uint_as_float((unsigned)(v & 0xffffffffull));
}
__device__ __forceinline__ float f2hi(ull v) {
    return __uint_as_float((unsigned)(v >> 32));
}
__device__ __forceinline__ float ex2f(float x) {
    float r;
    asm("ex2.approx.ftz.f32 %0, %1;" : "=f"(r) : "f"(x));
    return r;
}
__device__ __forceinline__ float lg2f(float x) {
    float r;
    asm("lg2.approx.ftz.f32 %0, %1;" : "=f"(r) : "f"(x));
    return r;
}

// ============================================================
// Kernel 1 (R10 exact, measured ~7.9us): 8 rows/block, 128 thr,
// thread-owns-column GEMM, stride-85 smem reduce, log2 tail.
// ============================================================
#define K1_ROWS 8
#define K1_THR 128
#define RSTR 85

__global__ void __launch_bounds__(K1_THR) rowstats_kernel(
    const float* __restrict__ zc, const float* __restrict__ zb,
    const float* __restrict__ Wc, const float* __restrict__ bc,
    const float* __restrict__ Wb, const float* __restrict__ bb,
    const int* __restrict__ y)
{
    __shared__ float red[K1_THR * RSTR];     // 43.5 KB partials
    __shared__ float vals[K1_ROWS][20];      // reduced raw logits

    const int t = threadIdx.x;
    const int vr0 = blockIdx.x * K1_ROWS;
    const int side = vr0 >> 11;
    const int grow0 = vr0 & (N - 1);

    const float4* z4 = (const float4*)((side ? zb : zc) + (size_t)grow0 * D);

    for (int h = 0; h < 2; h++) {
        const float4* w4 = (const float4*)(h ? Wb : Wc);
        float acc[K1_ROWS][10];
#pragma unroll
        for (int r = 0; r < K1_ROWS; r++)
#pragma unroll
            for (int c = 0; c < 10; c++) acc[r][c] = 0.f;

#pragma unroll
        for (int kk = 0; kk < 2; kk++) {
            const int d4 = t + kk * K1_THR;
            float4 zv[K1_ROWS];
#pragma unroll
            for (int r = 0; r < K1_ROWS; r++) zv[r] = z4[r * 256 + d4];
#pragma unroll
            for (int c = 0; c < 10; c++) {
                const float4 wv = w4[c * 256 + d4];
#pragma unroll
                for (int r = 0; r < K1_ROWS; r++) {
                    acc[r][c] = fmaf(zv[r].x, wv.x,
                                fmaf(zv[r].y, wv.y,
                                fmaf(zv[r].z, wv.z,
                                fmaf(zv[r].w, wv.w, acc[r][c]))));
                }
            }
        }

#pragma unroll
        for (int r = 0; r < K1_ROWS; r++)
#pragma unroll
            for (int c = 0; c < 10; c++)
                red[t * RSTR + r * 10 + c] = acc[r][c];
        __syncthreads();

        if (t < 80) {
            float s0 = 0.f, s1 = 0.f, s2 = 0.f, s3 = 0.f;
#pragma unroll 8
            for (int u = 0; u < K1_THR; u += 4) {
                s0 += red[(u + 0) * RSTR + t];
                s1 += red[(u + 1) * RSTR + t];
                s2 += red[(u + 2) * RSTR + t];
                s3 += red[(u + 3) * RSTR + t];
            }
            vals[t / 10][h * 10 + t % 10] = (s0 + s1) + (s2 + s3);
        }
        __syncthreads();
    }

    if (t < K1_ROWS) {
        const int row = grow0 + t;
        float v[20];
#pragma unroll
        for (int k = 0; k < 20; k++) v[k] = vals[t][k];
        if (side == 0) {
#pragma unroll
            for (int k = 0; k < 10; k++) { v[k] += bc[k]; v[10 + k] += bb[k]; }
        }
#pragma unroll
        for (int k = 0; k < 20; k++) v[k] *= INV_LN2;
        float mc = v[0], mb = v[10];
#pragma unroll
        for (int k = 1; k < 10; k++) {
            mc = fmaxf(mc, v[k]);
            mb = fmaxf(mb, v[10 + k]);
        }
        const int yr = y[row];
        if (side == 0) {
#pragma unroll
            for (int c = 0; c < 10; c++) {
                g_iEA2[row * CP2 + 2 * c]     = ex2f(v[c] - mc);
                g_iEA2[row * CP2 + 2 * c + 1] = ex2f(v[10 + c] - mb);
                g_iAbpM[row * CPS + c] = v[10 + c] - mb;
            }
            g_iacyM[row] = v[yr] - mc;
            g_iabyM[row] = v[10 + yr] - mb;
        } else {
#pragma unroll
            for (int c = 0; c < 10; c++) {
                g_jEB2[row * CP2 + 2 * c]     = ex2f(v[c] - mc);
                g_jEB2[row * CP2 + 2 * c + 1] = ex2f(v[10 + c] - mb);
                g_jCB[row * 10 + c] = make_float2(mc - v[c], mb - v[10 + c]);
            }
            g_jbbyM[row] = v[10 + yr] - mb;
        }
    }
}

// ============================================================
// Kernel 2 (R9 exact, best measured 17.06us): 64x64 tile,
// 256 threads, 4x4 per thread, j rows {tx,+16,+32,+48},
// log2-domain epilogue, 4 blocks/SM. Do not add live arrays:
// register budget is exactly consumed (spill cliff at +anything).
// ============================================================
__global__ void __launch_bounds__(256, 4) pair_kernel(
    const int* __restrict__ y, float* __restrict__ out)
{
    __shared__ __align__(16) float sEA2[64 * CP2];
    __shared__ __align__(16) float sEB2[64 * CP2];
    __shared__ __align__(16) ull   sCB[64 * 10];
    __shared__ float sAbpM[64 * CPS];
    __shared__ float sacyM[64], sabyM[64], sbbyM[64];
    __shared__ int   syi[64], syj[64];

    const int i0 = blockIdx.y * 64;
    const int j0 = blockIdx.x * 64;
    const int tid = threadIdx.x;

    for (int idx = tid; idx < 64 * (CP2 / 4); idx += 256) {
        ((float4*)sEA2)[idx] = ((const float4*)g_iEA2)[i0 * (CP2 / 4) + idx];
        ((float4*)sEB2)[idx] = ((const float4*)g_jEB2)[j0 * (CP2 / 4) + idx];
    }
    for (int idx = tid; idx < 64 * 5; idx += 256)
        ((float4*)sCB)[idx] = ((const float4*)g_jCB)[j0 * 5 + idx];
    for (int idx = tid; idx < 64 * CPS; idx += 256)
        sAbpM[idx] = g_iAbpM[i0 * CPS + idx];
    if (tid < 64) {
        sacyM[tid] = g_iacyM[i0 + tid];
        sabyM[tid] = g_iabyM[i0 + tid];
        syi[tid]   = y[i0 + tid];
    } else if (tid < 128) {
        const int u = tid - 64;
        sbbyM[u] = g_jbbyM[j0 + u];
        syj[u]   = y[j0 + u];
    }
    __syncthreads();

    const int tx = tid & 15;
    const int ty = tid >> 4;
    const int il = ty * 4;

    ull acc[4][4];
#pragma unroll
    for (int a = 0; a < 4; a++)
#pragma unroll
        for (int b = 0; b < 4; b++) acc[a][b] = 0ull;

#pragma unroll
    for (int g = 0; g < 5; g++) {
        ulonglong2 ea[4], eb[4];
#pragma unroll
        for (int a = 0; a < 4; a++)
            ea[a] = *(const ulonglong2*)&sEA2[(il + a) * CP2 + g * 4];
#pragma unroll
        for (int b = 0; b < 4; b++)
            eb[b] = *(const ulonglong2*)&sEB2[(tx + 16 * b) * CP2 + g * 4];
#pragma unroll
        for (int a = 0; a < 4; a++)
#pragma unroll
            for (int b = 0; b < 4; b++) {
                fma2(acc[a][b], ea[a].x, eb[b].x);
                fma2(acc[a][b], ea[a].y, eb[b].y);
            }
    }

    float acy[4], aby[4];
    int   yia[4];
#pragma unroll
    for (int a = 0; a < 4; a++) {
        acy[a] = sacyM[il + a];
        aby[a] = sabyM[il + a];
        yia[a] = syi[il + a];
    }
    float bby[4];
    int   yjb[4], jr[4];
#pragma unroll
    for (int b = 0; b < 4; b++) {
        jr[b]  = tx + 16 * b;
        bby[b] = sbbyM[jr[b]];
        yjb[b] = syj[jr[b]];
    }

#pragma unroll
    for (int a = 0; a < 4; a++) {
        float* orow = out + (size_t)(i0 + il + a) * N + j0;
#pragma unroll
        for (int b = 0; b < 4; b++) {
            const float lc2 = lg2f(f2lo(acc[a][b]));
            const float lb2 = lg2f(f2hi(acc[a][b]));
            const ull  cb = sCB[jr[b] * 10 + yia[a]];
            const float ce_pc2 = lc2 - acy[a] + f2lo(cb);
            const float ce_pb2 = lb2 - aby[a] + f2hi(cb);
            const float logp2  = sAbpM[(il + a) * CPS + yjb[b]] + bby[b] - lb2;
            const float gce2   = -logp2 * ex2f(GCE_Q * logp2);
            const float wr = __fdividef(ce_pb2, ce_pc2 + ce_pb2 + EPS2);
            orow[jr[b]] = fmaf(wr, ce_pc2 - gce2, gce2) * LN2;
        }
    }
}

// ============================================================
extern "C" void kernel_launch(void* const* d_in, const int* in_sizes, int n_in,
                              void* d_out, int out_size)
{
    const float* zc = (const float*)d_in[0];  // [N, D]
    const float* zb = (const float*)d_in[1];  // [N, D]
    const float* Wc = (const float*)d_in[2];  // [C, D]
    const float* bc = (const float*)d_in[3];  // [C]
    const float* Wb = (const float*)d_in[4];  // [C, D]
    const float* bb = (const float*)d_in[5];  // [C]
    const int*   y  = (const int*)d_in[6];    // [N]
    float* out = (float*)d_out;               // [N, N]

    rowstats_kernel<<<(2 * N) / K1_ROWS, K1_THR>>>(zc, zb, Wc, bc, Wb, bb, y);

    dim3 g2(N / 64, N / 64);
    pair_kernel<<<g2, 256>>>(y, out);
}

// round 15
// speedup vs baseline: 2.5727x; 1.0522x over previous
#include <cuda_runtime.h>
#include <cstdint>

#define N 2048
#define D 1024
#define GCE_Q 0.7f
#define EPS 1e-8f
#define INV_LN2 1.4426950408889634f
#define LN2 0.6931471805599453f
#define EPS2 (EPS * INV_LN2)

#define CP2 20   // interleaved exp row stride: 10 classes x 2 heads
#define CPS 13   // scalar raw row stride (odd -> conflict-free)

typedef unsigned long long ull;

// -------- device scratch (no allocations) --------
// All log-domain tables stored in log2 units (divided by ln2).
__device__ __align__(16) float g_iEA2[N * CP2];  // i-side interleaved exp(v-m): [row][c][head]
__device__ __align__(16) float g_jEB2[N * CP2];  // j-side interleaved
__device__ float g_iAbpM[N * CPS];               // (Ab'[i,c] - mAb[i]) / ln2
__device__ __align__(16) float2 g_jCB[N * 10];   // ((mBc - Bc[j,c])/ln2, (mBb - Bb[j,c])/ln2)
__device__ float g_iacyM[N];                     // (Ac'[i,y[i]] - mAc[i]) / ln2
__device__ float g_iabyM[N];                     // (Ab'[i,y[i]] - mAb[i]) / ln2
__device__ float g_jbbyM[N];                     // (Bb[j,y[j]] - mBb[j]) / ln2

__device__ __forceinline__ void fma2(ull& acc, ull a, ull b) {
    asm("fma.rn.f32x2 %0, %1, %2, %0;" : "+l"(acc) : "l"(a), "l"(b));
}
__device__ __forceinline__ float f2lo(ull v) {
    return __uint_as_float((unsigned)(v & 0xffffffffull));
}
__device__ __forceinline__ float f2hi(ull v) {
    return __uint_as_float((unsigned)(v >> 32));
}
__device__ __forceinline__ float ex2f(float x) {
    float r;
    asm("ex2.approx.ftz.f32 %0, %1;" : "=f"(r) : "f"(x));
    return r;
}
__device__ __forceinline__ float lg2f(float x) {
    float r;
    asm("lg2.approx.ftz.f32 %0, %1;" : "=f"(r) : "f"(x));
    return r;
}

// ============================================================
// Kernel 1 v2: 4 rows/block, 128 thr, thread-owns-column GEMM
// with PACKED f32x2 accumulation (halves the FFMA issue floor).
// acc = ull[4][10] (80 regs) + hoisted z (32 regs): fits, no spill.
// Stride-41 smem reduce, log2-domain softmax tail.
// ============================================================
#define K1_ROWS 4
#define K1_THR 128
#define RSTR2 41

__global__ void __launch_bounds__(K1_THR) rowstats_kernel(
    const float* __restrict__ zc, const float* __restrict__ zb,
    const float* __restrict__ Wc, const float* __restrict__ bc,
    const float* __restrict__ Wb, const float* __restrict__ bb,
    const int* __restrict__ y)
{
    __shared__ float red[K1_THR * RSTR2];    // 21 KB partials
    __shared__ float vals[K1_ROWS][20];      // reduced raw logits

    const int t = threadIdx.x;
    const int vr0 = blockIdx.x * K1_ROWS;
    const int side = vr0 >> 11;              // 0 -> z_c, 1 -> z_b
    const int grow0 = vr0 & (N - 1);

    const ulonglong2* z2 = (const ulonglong2*)((side ? zb : zc) + (size_t)grow0 * D);

    // hoist z: rows r, both kk halves (each ulonglong2 = one float4)
    ulonglong2 zv[2][K1_ROWS];
#pragma unroll
    for (int kk = 0; kk < 2; kk++)
#pragma unroll
        for (int r = 0; r < K1_ROWS; r++)
            zv[kk][r] = z2[r * 256 + t + kk * K1_THR];

    for (int h = 0; h < 2; h++) {
        const ulonglong2* w2 = (const ulonglong2*)(h ? Wb : Wc);
        ull acc[K1_ROWS][10];
#pragma unroll
        for (int r = 0; r < K1_ROWS; r++)
#pragma unroll
            for (int c = 0; c < 10; c++) acc[r][c] = 0ull;

#pragma unroll
        for (int kk = 0; kk < 2; kk++) {
            const int d = t + kk * K1_THR;
#pragma unroll
            for (int c = 0; c < 10; c++) {
                const ulonglong2 wv = w2[c * 256 + d];
#pragma unroll
                for (int r = 0; r < K1_ROWS; r++) {
                    fma2(acc[r][c], zv[kk][r].x, wv.x);
                    fma2(acc[r][c], zv[kk][r].y, wv.y);
                }
            }
        }

        // collapse packed halves, dump (stride 41: odd -> conflict-free)
#pragma unroll
        for (int r = 0; r < K1_ROWS; r++)
#pragma unroll
            for (int c = 0; c < 10; c++)
                red[t * RSTR2 + r * 10 + c] = f2lo(acc[r][c]) + f2hi(acc[r][c]);
        __syncthreads();

        if (t < 40) {
            float s0 = 0.f, s1 = 0.f, s2 = 0.f, s3 = 0.f;
#pragma unroll 8
            for (int u = 0; u < K1_THR; u += 4) {
                s0 += red[(u + 0) * RSTR2 + t];
                s1 += red[(u + 1) * RSTR2 + t];
                s2 += red[(u + 2) * RSTR2 + t];
                s3 += red[(u + 3) * RSTR2 + t];
            }
            vals[t / 10][h * 10 + t % 10] = (s0 + s1) + (s2 + s3);
        }
        __syncthreads();
    }

    // log2-domain softmax tail: one thread per block row
    if (t < K1_ROWS) {
        const int row = grow0 + t;
        float v[20];
#pragma unroll
        for (int k = 0; k < 20; k++) v[k] = vals[t][k];
        if (side == 0) {
#pragma unroll
            for (int k = 0; k < 10; k++) { v[k] += bc[k]; v[10 + k] += bb[k]; }
        }
#pragma unroll
        for (int k = 0; k < 20; k++) v[k] *= INV_LN2;
        float mc = v[0], mb = v[10];
#pragma unroll
        for (int k = 1; k < 10; k++) {
            mc = fmaxf(mc, v[k]);
            mb = fmaxf(mb, v[10 + k]);
        }
        const int yr = y[row];
        if (side == 0) {
#pragma unroll
            for (int c = 0; c < 10; c++) {
                g_iEA2[row * CP2 + 2 * c]     = ex2f(v[c] - mc);
                g_iEA2[row * CP2 + 2 * c + 1] = ex2f(v[10 + c] - mb);
                g_iAbpM[row * CPS + c] = v[10 + c] - mb;
            }
            g_iacyM[row] = v[yr] - mc;
            g_iabyM[row] = v[10 + yr] - mb;
        } else {
#pragma unroll
            for (int c = 0; c < 10; c++) {
                g_jEB2[row * CP2 + 2 * c]     = ex2f(v[c] - mc);
                g_jEB2[row * CP2 + 2 * c + 1] = ex2f(v[10 + c] - mb);
                g_jCB[row * 10 + c] = make_float2(mc - v[c], mb - v[10 + c]);
            }
            g_jbbyM[row] = v[10 + yr] - mb;
        }
    }
}

// ============================================================
// Kernel 2 (R9 exact, best measured 17.06us): 64x64 tile,
// 256 threads, 4x4 per thread, j rows {tx,+16,+32,+48},
// log2-domain epilogue, 4 blocks/SM. Do not add live arrays:
// register budget is exactly consumed (spill cliff at +anything).
// ============================================================
__global__ void __launch_bounds__(256, 4) pair_kernel(
    const int* __restrict__ y, float* __restrict__ out)
{
    __shared__ __align__(16) float sEA2[64 * CP2];
    __shared__ __align__(16) float sEB2[64 * CP2];
    __shared__ __align__(16) ull   sCB[64 * 10];
    __shared__ float sAbpM[64 * CPS];
    __shared__ float sacyM[64], sabyM[64], sbbyM[64];
    __shared__ int   syi[64], syj[64];

    const int i0 = blockIdx.y * 64;
    const int j0 = blockIdx.x * 64;
    const int tid = threadIdx.x;

    for (int idx = tid; idx < 64 * (CP2 / 4); idx += 256) {
        ((float4*)sEA2)[idx] = ((const float4*)g_iEA2)[i0 * (CP2 / 4) + idx];
        ((float4*)sEB2)[idx] = ((const float4*)g_jEB2)[j0 * (CP2 / 4) + idx];
    }
    for (int idx = tid; idx < 64 * 5; idx += 256)
        ((float4*)sCB)[idx] = ((const float4*)g_jCB)[j0 * 5 + idx];
    for (int idx = tid; idx < 64 * CPS; idx += 256)
        sAbpM[idx] = g_iAbpM[i0 * CPS + idx];
    if (tid < 64) {
        sacyM[tid] = g_iacyM[i0 + tid];
        sabyM[tid] = g_iabyM[i0 + tid];
        syi[tid]   = y[i0 + tid];
    } else if (tid < 128) {
        const int u = tid - 64;
        sbbyM[u] = g_jbbyM[j0 + u];
        syj[u]   = y[j0 + u];
    }
    __syncthreads();

    const int tx = tid & 15;
    const int ty = tid >> 4;
    const int il = ty * 4;

    ull acc[4][4];
#pragma unroll
    for (int a = 0; a < 4; a++)
#pragma unroll
        for (int b = 0; b < 4; b++) acc[a][b] = 0ull;

#pragma unroll
    for (int g = 0; g < 5; g++) {
        ulonglong2 ea[4], eb[4];
#pragma unroll
        for (int a = 0; a < 4; a++)
            ea[a] = *(const ulonglong2*)&sEA2[(il + a) * CP2 + g * 4];
#pragma unroll
        for (int b = 0; b < 4; b++)
            eb[b] = *(const ulonglong2*)&sEB2[(tx + 16 * b) * CP2 + g * 4];
#pragma unroll
        for (int a = 0; a < 4; a++)
#pragma unroll
            for (int b = 0; b < 4; b++) {
                fma2(acc[a][b], ea[a].x, eb[b].x);
                fma2(acc[a][b], ea[a].y, eb[b].y);
            }
    }

    float acy[4], aby[4];
    int   yia[4];
#pragma unroll
    for (int a = 0; a < 4; a++) {
        acy[a] = sacyM[il + a];
        aby[a] = sabyM[il + a];
        yia[a] = syi[il + a];
    }
    float bby[4];
    int   yjb[4], jr[4];
#pragma unroll
    for (int b = 0; b < 4; b++) {
        jr[b]  = tx + 16 * b;
        bby[b] = sbbyM[jr[b]];
        yjb[b] = syj[jr[b]];
    }

#pragma unroll
    for (int a = 0; a < 4; a++) {
        float* orow = out + (size_t)(i0 + il + a) * N + j0;
#pragma unroll
        for (int b = 0; b < 4; b++) {
            const float lc2 = lg2f(f2lo(acc[a][b]));
            const float lb2 = lg2f(f2hi(acc[a][b]));
            const ull  cb = sCB[jr[b] * 10 + yia[a]];
            const float ce_pc2 = lc2 - acy[a] + f2lo(cb);
            const float ce_pb2 = lb2 - aby[a] + f2hi(cb);
            const float logp2  = sAbpM[(il + a) * CPS + yjb[b]] + bby[b] - lb2;
            const float gce2   = -logp2 * ex2f(GCE_Q * logp2);
            const float wr = __fdividef(ce_pb2, ce_pc2 + ce_pb2 + EPS2);
            orow[jr[b]] = fmaf(wr, ce_pc2 - gce2, gce2) * LN2;
        }
    }
}

// ============================================================
extern "C" void kernel_launch(void* const* d_in, const int* in_sizes, int n_in,
                              void* d_out, int out_size)
{
    const float* zc = (const float*)d_in[0];  // [N, D]
    const float* zb = (const float*)d_in[1];  // [N, D]
    const float* Wc = (const float*)d_in[2];  // [C, D]
    const float* bc = (const float*)d_in[3];  // [C]
    const float* Wb = (const float*)d_in[4];  // [C, D]
    const float* bb = (const float*)d_in[5];  // [C]
    const int*   y  = (const int*)d_in[6];    // [N]
    float* out = (float*)d_out;               // [N, N]

    rowstats_kernel<<<(2 * N) / K1_ROWS, K1_THR>>>(zc, zb, Wc, bc, Wb, bb, y);

    dim3 g2(N / 64, N / 64);
    pair_kernel<<<g2, 256>>>(y, out);
}